// round 2
// baseline (speedup 1.0000x reference)
#include <cuda_runtime.h>
#include <cstdint>

// Problem dims
#define B_    512
#define T_    128
#define ID_   128
#define HD_   256
#define G4_   1024   // 4*HD
#define KT_   384    // ID + HD
#define OUTD_ 128
#define RPC   8      // batch rows per LSTM CTA

// ---------------- scratch (static device globals; no allocation) ----------------
__device__ float g_Wcat[2][KT_][G4_];                 // [dir][k][4H]  (Wi rows then Wh rows)
__device__ float g_bias[2][G4_];                      // bi + bh per dir
__device__ float g_x1[(size_t)B_ * T_ * 2 * HD_];     // bi-LSTM hidden states, 134 MB
__device__ float g_x2[(size_t)B_ * T_ * HD_];         // 67 MB
__device__ float g_x3[(size_t)B_ * T_ * HD_];         // 67 MB
__device__ float g_x4[(size_t)B_ * T_ * OUTD_];       // 33 MB

// ---------------- helpers ----------------
__device__ __forceinline__ unsigned long long fma2(unsigned long long a, unsigned long long b,
                                                   unsigned long long c) {
    unsigned long long d;
    asm("fma.rn.f32x2 %0, %1, %2, %3;" : "=l"(d) : "l"(a), "l"(b), "l"(c));
    return d;
}
__device__ __forceinline__ unsigned long long dupf(float v) {
    unsigned long long r;
    unsigned u = __float_as_uint(v);
    asm("mov.b64 %0, {%1, %1};" : "=l"(r) : "r"(u));
    return r;
}
__device__ __forceinline__ float lo32(unsigned long long v) { return __uint_as_float((unsigned)v); }
__device__ __forceinline__ float hi32(unsigned long long v) { return __uint_as_float((unsigned)(v >> 32)); }
__device__ __forceinline__ float sigm(float x) { return 1.f / (1.f + __expf(-x)); }

// ---------------- prep: pack [Wi;Wh] and bi+bh per direction ----------------
__global__ void prep_kernel(const float* __restrict__ Wi_f, const float* __restrict__ Wh_f,
                            const float* __restrict__ bi_f, const float* __restrict__ bh_f,
                            const float* __restrict__ Wi_r, const float* __restrict__ Wh_r,
                            const float* __restrict__ bi_r, const float* __restrict__ bh_r) {
    int idx = blockIdx.x * blockDim.x + threadIdx.x;
    int stride = gridDim.x * blockDim.x;
    const int total = KT_ * G4_;
    for (int i = idx; i < total; i += stride) {
        int k = i / G4_, n = i - k * G4_;
        g_Wcat[0][k][n] = (k < ID_) ? Wi_f[k * G4_ + n] : Wh_f[(k - ID_) * G4_ + n];
        g_Wcat[1][k][n] = (k < ID_) ? Wi_r[k * G4_ + n] : Wh_r[(k - ID_) * G4_ + n];
    }
    for (int i = idx; i < G4_; i += stride) {
        g_bias[0][i] = bi_f[i] + bh_f[i];
        g_bias[1][i] = bi_r[i] + bh_r[i];
    }
}

// ---------------- persistent bidirectional LSTM ----------------
// 128 CTAs: CTA 0..63 = forward (8 batch rows each), 64..127 = reverse.
// No inter-CTA dependency: recurrence is independent per batch row.
__global__ __launch_bounds__(256, 1) void lstm_kernel(const float* __restrict__ x0) {
    __shared__ __align__(16) float sm_xh[KT_][RPC];   // [k][row]: k<ID -> x_t, k>=ID -> h
    __shared__ __align__(16) float sm_g[G4_][RPC];    // gates

    const int tid = threadIdx.x;
    const int dir = blockIdx.x >> 6;
    const int b0 = (blockIdx.x & 63) * RPC;

    const float* Wc = &g_Wcat[dir][0][0] + 4 * tid;   // this thread's 4 contiguous gate cols
    const float4 bias = *(const float4*)&g_bias[dir][4 * tid];

    float cst[RPC];
#pragma unroll
    for (int r = 0; r < RPC; r++) cst[r] = 0.f;

    // zero initial h region
    float* hz = &sm_xh[ID_][0];
    for (int i = tid; i < HD_ * RPC; i += 256) hz[i] = 0.f;

    const int xr_row = tid >> 5, xl = tid & 31;
    const float* xbase = x0 + ((size_t)(b0 + xr_row) * T_) * ID_;

    for (int t = 0; t < T_; t++) {
        const int ts = dir ? (T_ - 1 - t) : t;
        const float* xr = xbase + (size_t)ts * ID_;
#pragma unroll
        for (int j = 0; j < 4; j++) sm_xh[xl + 32 * j][xr_row] = xr[xl + 32 * j];
        __syncthreads();   // x + h visible to everyone

        // gates[8 rows][4 cols] via f32x2: acc[rowpair][col]
        unsigned long long acc[4][4];
#pragma unroll
        for (int rp = 0; rp < 4; rp++)
#pragma unroll
            for (int c = 0; c < 4; c++) acc[rp][c] = 0ull;

#pragma unroll 4
        for (int k = 0; k < KT_; k++) {
            float4 w = *(const float4*)(Wc + (size_t)k * G4_);
            unsigned long long wd0 = dupf(w.x), wd1 = dupf(w.y), wd2 = dupf(w.z), wd3 = dupf(w.w);
#pragma unroll
            for (int rp = 0; rp < 4; rp++) {
                unsigned long long hp = *(const unsigned long long*)&sm_xh[k][2 * rp];
                acc[rp][0] = fma2(hp, wd0, acc[rp][0]);
                acc[rp][1] = fma2(hp, wd1, acc[rp][1]);
                acc[rp][2] = fma2(hp, wd2, acc[rp][2]);
                acc[rp][3] = fma2(hp, wd3, acc[rp][3]);
            }
        }

        // dump gates (+bias) to smem for the cross-gate cell update
        const float bv[4] = {bias.x, bias.y, bias.z, bias.w};
#pragma unroll
        for (int c = 0; c < 4; c++) {
#pragma unroll
            for (int rp = 0; rp < 4; rp++) {
                sm_g[4 * tid + c][2 * rp]     = lo32(acc[rp][c]) + bv[c];
                sm_g[4 * tid + c][2 * rp + 1] = hi32(acc[rp][c]) + bv[c];
            }
        }
        __syncthreads();   // gates visible; all sm_xh reads done

        // cell update: thread tid owns hidden dim hd = tid for all 8 rows
        const int hd = tid;
        float* x1p = g_x1 + ((size_t)b0 * T_ + t) * (2 * HD_) + (size_t)dir * HD_ + hd;
#pragma unroll
        for (int r = 0; r < RPC; r++) {
            float gf = sm_g[hd][r];
            float gi = sm_g[HD_ + hd][r];
            float ga = sm_g[2 * HD_ + hd][r];
            float go = sm_g[3 * HD_ + hd][r];
            float f = sigm(gf), ii = sigm(gi), a = tanhf(ga), o = sigm(go);
            float cc = f * cst[r] + ii * a;
            cst[r] = cc;
            float h = o * tanhf(cc);
            sm_xh[ID_ + hd][r] = h;                       // feed next step
            x1p[(size_t)r * T_ * 2 * HD_] = h;            // coalesced across threads
        }
        // next iteration's top __syncthreads orders h-writes vs next GEMM
    }
}

// ---------------- generic fp32x2 GEMM with bias + optional leaky-relu ----------------
// C[M,N] = act(A[M,K] @ W[K,N] + bias), tiles 64x128x16, 256 threads, thread = 8x4.
template <int ACT>
__global__ __launch_bounds__(256) void gemm_kernel(const float* __restrict__ A,
                                                   const float* __restrict__ W,
                                                   const float* __restrict__ bias,
                                                   float* __restrict__ C,
                                                   int M, int N, int K) {
    __shared__ __align__(16) float smA[16][64];
    __shared__ __align__(16) float smW[16][128];

    const int tid = threadIdx.x;
    const int n0 = blockIdx.x * 128;
    const int m0 = blockIdx.y * 64;
    const int col = (tid & 31) * 4;      // 0..124
    const int rg = (tid >> 5) * 8;       // 0..56

    unsigned long long acc[4][4];
#pragma unroll
    for (int rp = 0; rp < 4; rp++)
#pragma unroll
        for (int c = 0; c < 4; c++) acc[rp][c] = 0ull;

    const int la_r = tid >> 2;           // 0..63
    const int la_k = (tid & 3) * 4;      // 0,4,8,12
    const int lw_n = (tid & 31) * 4;
    const int lw_k = tid >> 5;           // 0..7

    for (int k0 = 0; k0 < K; k0 += 16) {
        float4 av = *(const float4*)&A[(size_t)(m0 + la_r) * K + k0 + la_k];
        smA[la_k + 0][la_r] = av.x;
        smA[la_k + 1][la_r] = av.y;
        smA[la_k + 2][la_r] = av.z;
        smA[la_k + 3][la_r] = av.w;
        *(float4*)&smW[lw_k][lw_n]     = *(const float4*)&W[(size_t)(k0 + lw_k) * N + n0 + lw_n];
        *(float4*)&smW[lw_k + 8][lw_n] = *(const float4*)&W[(size_t)(k0 + lw_k + 8) * N + n0 + lw_n];
        __syncthreads();

#pragma unroll
        for (int kk = 0; kk < 16; kk++) {
            float4 wv = *(const float4*)&smW[kk][col];
            unsigned long long wd0 = dupf(wv.x), wd1 = dupf(wv.y), wd2 = dupf(wv.z), wd3 = dupf(wv.w);
#pragma unroll
            for (int rp = 0; rp < 4; rp++) {
                unsigned long long hp = *(const unsigned long long*)&smA[kk][rg + 2 * rp];
                acc[rp][0] = fma2(hp, wd0, acc[rp][0]);
                acc[rp][1] = fma2(hp, wd1, acc[rp][1]);
                acc[rp][2] = fma2(hp, wd2, acc[rp][2]);
                acc[rp][3] = fma2(hp, wd3, acc[rp][3]);
            }
        }
        __syncthreads();
    }

    const float4 bv = *(const float4*)&bias[n0 + col];
#pragma unroll
    for (int rp = 0; rp < 4; rp++) {
        const int row0 = m0 + rg + 2 * rp;
        float4 v0, v1;
        v0.x = lo32(acc[rp][0]) + bv.x; v0.y = lo32(acc[rp][1]) + bv.y;
        v0.z = lo32(acc[rp][2]) + bv.z; v0.w = lo32(acc[rp][3]) + bv.w;
        v1.x = hi32(acc[rp][0]) + bv.x; v1.y = hi32(acc[rp][1]) + bv.y;
        v1.z = hi32(acc[rp][2]) + bv.z; v1.w = hi32(acc[rp][3]) + bv.w;
        if (ACT) {   // leaky_relu(0.1): max(v, 0.1*v)
            v0.x = fmaxf(v0.x, 0.1f * v0.x); v0.y = fmaxf(v0.y, 0.1f * v0.y);
            v0.z = fmaxf(v0.z, 0.1f * v0.z); v0.w = fmaxf(v0.w, 0.1f * v0.w);
            v1.x = fmaxf(v1.x, 0.1f * v1.x); v1.y = fmaxf(v1.y, 0.1f * v1.y);
            v1.z = fmaxf(v1.z, 0.1f * v1.z); v1.w = fmaxf(v1.w, 0.1f * v1.w);
        }
        *(float4*)&C[(size_t)row0 * N + n0 + col]       = v0;
        *(float4*)&C[(size_t)(row0 + 1) * N + n0 + col] = v1;
    }
}

// ---------------- head: sigmoid[0:64], softmax segments (64,72),(72,88),(88,128) ----------------
__global__ __launch_bounds__(256) void head_kernel(float* __restrict__ out) {
    const int row = blockIdx.x * blockDim.x + threadIdx.x;
    if (row >= B_ * T_) return;
    const float* x = g_x4 + (size_t)row * OUTD_;
    float* o = out + (size_t)row * OUTD_;

#pragma unroll 4
    for (int j = 0; j < 64; j++) o[j] = sigm(x[j]);

    {   // segment [64,72)
        float e[8]; float mx = -1e30f;
#pragma unroll
        for (int j = 0; j < 8; j++) { e[j] = x[64 + j]; mx = fmaxf(mx, e[j]); }
        float s = 0.f;
#pragma unroll
        for (int j = 0; j < 8; j++) { e[j] = __expf(e[j] - mx); s += e[j]; }
        float inv = 1.f / s;
#pragma unroll
        for (int j = 0; j < 8; j++) o[64 + j] = e[j] * inv;
    }
    {   // segment [72,88)
        float e[16]; float mx = -1e30f;
#pragma unroll
        for (int j = 0; j < 16; j++) { e[j] = x[72 + j]; mx = fmaxf(mx, e[j]); }
        float s = 0.f;
#pragma unroll
        for (int j = 0; j < 16; j++) { e[j] = __expf(e[j] - mx); s += e[j]; }
        float inv = 1.f / s;
#pragma unroll
        for (int j = 0; j < 16; j++) o[72 + j] = e[j] * inv;
    }
    {   // segment [88,128)
        float e[40]; float mx = -1e30f;
#pragma unroll
        for (int j = 0; j < 40; j++) { e[j] = x[88 + j]; mx = fmaxf(mx, e[j]); }
        float s = 0.f;
#pragma unroll
        for (int j = 0; j < 40; j++) { e[j] = __expf(e[j] - mx); s += e[j]; }
        float inv = 1.f / s;
#pragma unroll
        for (int j = 0; j < 40; j++) o[88 + j] = e[j] * inv;
    }
}

// ---------------- launch ----------------
extern "C" void kernel_launch(void* const* d_in, const int* in_sizes, int n_in,
                              void* d_out, int out_size) {
    (void)in_sizes; (void)n_in; (void)out_size;
    const float* x0   = (const float*)d_in[0];
    const float* Wi_f = (const float*)d_in[1];
    const float* bi_f = (const float*)d_in[2];
    const float* Wh_f = (const float*)d_in[3];
    const float* bh_f = (const float*)d_in[4];
    const float* Wi_r = (const float*)d_in[5];
    const float* bi_r = (const float*)d_in[6];
    const float* Wh_r = (const float*)d_in[7];
    const float* bh_r = (const float*)d_in[8];
    const float* W1   = (const float*)d_in[9];
    const float* b1   = (const float*)d_in[10];
    const float* W2   = (const float*)d_in[11];
    const float* b2   = (const float*)d_in[12];
    const float* W3   = (const float*)d_in[13];
    const float* b3   = (const float*)d_in[14];
    float* out = (float*)d_out;

    float *p_x1, *p_x2, *p_x3, *p_x4;
    cudaGetSymbolAddress((void**)&p_x1, g_x1);
    cudaGetSymbolAddress((void**)&p_x2, g_x2);
    cudaGetSymbolAddress((void**)&p_x3, g_x3);
    cudaGetSymbolAddress((void**)&p_x4, g_x4);

    prep_kernel<<<128, 256>>>(Wi_f, Wh_f, bi_f, bh_f, Wi_r, Wh_r, bi_r, bh_r);
    lstm_kernel<<<128, 256>>>(x0);

    const int M = B_ * T_;
    // N=HD for gemm1 (K=2*HD): grid.x = N/128 = 2  (round-1 bug: was 2*HD_/128 = 4 -> OOB)
    gemm_kernel<1><<<dim3(HD_ / 128, M / 64), 256>>>(p_x1, W1, b1, p_x2, M, HD_, 2 * HD_);
    gemm_kernel<1><<<dim3(HD_ / 128, M / 64), 256>>>(p_x2, W2, b2, p_x3, M, HD_, HD_);
    gemm_kernel<0><<<dim3(OUTD_ / 128, M / 64), 256>>>(p_x3, W3, b3, p_x4, M, OUTD_, HD_);
    head_kernel<<<(M + 255) / 256, 256>>>(out);
}

// round 3
// speedup vs baseline: 1.1910x; 1.1910x over previous
#include <cuda_runtime.h>
#include <cstdint>

// Problem dims
#define B_    512
#define T_    128
#define ID_   128
#define HD_   256
#define G4_   1024   // 4*HD
#define KT_   384    // ID + HD
#define OUTD_ 128

typedef unsigned long long ull;

// ---------------- scratch (static device globals; no allocation) ----------------
__device__ float g_Wp[2][2][KT_][512];                // [dir][half][k][col] col = gate*128 + hd_local
__device__ float g_bp[2][2][512];                     // packed bi+bh
__device__ float g_x1[(size_t)B_ * T_ * 2 * HD_];     // bi-LSTM hidden states
__device__ float g_x2[(size_t)B_ * T_ * HD_];
__device__ float g_x3[(size_t)B_ * T_ * HD_];
__device__ float g_x4[(size_t)B_ * T_ * OUTD_];

// ---------------- helpers ----------------
__device__ __forceinline__ ull fma2(ull a, ull b, ull c) {
    ull d;
    asm("fma.rn.f32x2 %0, %1, %2, %3;" : "=l"(d) : "l"(a), "l"(b), "l"(c));
    return d;
}
__device__ __forceinline__ ull dupf(float v) {
    ull r; unsigned u = __float_as_uint(v);
    asm("mov.b64 %0, {%1, %1};" : "=l"(r) : "r"(u));
    return r;
}
__device__ __forceinline__ ull pack2(float a, float b) {
    ull r;
    asm("mov.b64 %0, {%1, %2};" : "=l"(r) : "r"(__float_as_uint(a)), "r"(__float_as_uint(b)));
    return r;
}
__device__ __forceinline__ float lo32(ull v) { return __uint_as_float((unsigned)v); }
__device__ __forceinline__ float hi32(ull v) { return __uint_as_float((unsigned)(v >> 32)); }
__device__ __forceinline__ float sigm(float x) { return 1.f / (1.f + __expf(-x)); }
__device__ __forceinline__ float tanhp(float x) { return fmaf(2.f, sigm(2.f * x), -1.f); }

#define CLUSTER_SYNC() do { \
    asm volatile("barrier.cluster.arrive.aligned;" ::: "memory"); \
    asm volatile("barrier.cluster.wait.aligned;" ::: "memory"); \
} while (0)

__device__ __forceinline__ void st_cluster64(unsigned addr, ull v) {
    asm volatile("st.shared::cluster.b64 [%0], %1;" :: "r"(addr), "l"(v) : "memory");
}

// ---------------- prep: pack per-(dir,half) weight slices + biases ----------------
__global__ void prep_kernel(const float* __restrict__ Wi_f, const float* __restrict__ Wh_f,
                            const float* __restrict__ bi_f, const float* __restrict__ bh_f,
                            const float* __restrict__ Wi_r, const float* __restrict__ Wh_r,
                            const float* __restrict__ bi_r, const float* __restrict__ bh_r) {
    int idx = blockIdx.x * blockDim.x + threadIdx.x;
    int stride = gridDim.x * blockDim.x;
    const int total = 2 * 2 * KT_ * 512;
    float* wflat = &g_Wp[0][0][0][0];
    for (int i = idx; i < total; i += stride) {
        int dir = i / (2 * KT_ * 512);
        int r = i % (2 * KT_ * 512);
        int half = r / (KT_ * 512);
        int r2 = r % (KT_ * 512);
        int k = r2 / 512, col = r2 % 512;
        int g = col >> 7, hl = col & 127;
        int sc = g * 256 + half * 128 + hl;
        const float* Wi = dir ? Wi_r : Wi_f;
        const float* Wh = dir ? Wh_r : Wh_f;
        wflat[i] = (k < ID_) ? Wi[k * G4_ + sc] : Wh[(k - ID_) * G4_ + sc];
    }
    float* bflat = &g_bp[0][0][0];
    for (int i = idx; i < 2 * 2 * 512; i += stride) {
        int dir = i / 1024, r = i % 1024;
        int half = r / 512, col = r % 512;
        int g = col >> 7, hl = col & 127;
        int sc = g * 256 + half * 128 + hl;
        bflat[i] = (dir ? (bi_r[sc] + bh_r[sc]) : (bi_f[sc] + bh_f[sc]));
    }
}

// ---------------- persistent clustered bidirectional LSTM ----------------
// 128 CTAs = 64 clusters of 2. Cluster cid: dir = cid>>5, batch rows = (cid&31)*16..+16.
// Each CTA computes gates for 128 hidden dims (its half) over 16 rows; halves exchange h via DSMEM.
// Weight prefetch: 4-deep rolling register buffer (distance-3 chunks hides L2 latency).
#define PREFW(p) { int _p = (p); int _kb = (_p < 96) ? _p * 4 : 380;               \
    const float2* _w = wbase + (size_t)_kb * 256;                                   \
    float2* _d = wv[_p & 3];                                                        \
    _d[0] = _w[0]; _d[1] = _w[256]; _d[2] = _w[512]; _d[3] = _w[768]; }

#define COMP4(bi, rowbase) { const float* _rb = (rowbase);                          \
    _Pragma("unroll") for (int _i = 0; _i < 4; _i++) {                              \
        float2 _w = wv[(bi) & 3][_i];                                               \
        ull w0 = dupf(_w.x), w1 = dupf(_w.y);                                       \
        const ulonglong2* _h = (const ulonglong2*)(_rb + _i * 16);                  \
        ulonglong2 hA = _h[0], hB = _h[1], hC = _h[2], hD = _h[3];                  \
        acc0[0] = fma2(hA.x, w0, acc0[0]); acc1[0] = fma2(hA.x, w1, acc1[0]);       \
        acc0[1] = fma2(hA.y, w0, acc0[1]); acc1[1] = fma2(hA.y, w1, acc1[1]);       \
        acc0[2] = fma2(hB.x, w0, acc0[2]); acc1[2] = fma2(hB.x, w1, acc1[2]);       \
        acc0[3] = fma2(hB.y, w0, acc0[3]); acc1[3] = fma2(hB.y, w1, acc1[3]);       \
        acc0[4] = fma2(hC.x, w0, acc0[4]); acc1[4] = fma2(hC.x, w1, acc1[4]);       \
        acc0[5] = fma2(hC.y, w0, acc0[5]); acc1[5] = fma2(hC.y, w1, acc1[5]);       \
        acc0[6] = fma2(hD.x, w0, acc0[6]); acc1[6] = fma2(hD.x, w1, acc1[6]);       \
        acc0[7] = fma2(hD.y, w0, acc0[7]); acc1[7] = fma2(hD.y, w1, acc1[7]); } }

__global__ __launch_bounds__(256, 1) __cluster_dims__(2, 1, 1)
void lstm_kernel(const float* __restrict__ x0) {
    extern __shared__ float smem[];
    float* sm_x = smem;                   // [128][16]
    float* sm_h = smem + 2048;            // [2][256][16] ping-pong
    float* sm_g = smem + 2048 + 8192;     // [16][512]

    const int tid = threadIdx.x;
    const int cid = blockIdx.x >> 1;
    const int dir = cid >> 5;
    const int b0 = (cid & 31) * 16;
    unsigned rank;
    asm("mov.u32 %0, %%cluster_ctarank;" : "=r"(rank));
    const int half = (int)rank;

    const float2* wbase = (const float2*)(&g_Wp[dir][half][0][0]) + tid;
    const float bs0 = g_bp[dir][half][2 * tid];
    const float bs1 = g_bp[dir][half][2 * tid + 1];

    // zero h buffer 0
    for (int i = tid; i < 4096; i += 256) sm_h[i] = 0.f;

    // x prefetch for t=0
    const int xr = tid >> 4, xc = (tid & 15) * 8;
    const float* xrow = x0 + ((size_t)(b0 + xr) * T_) * ID_ + xc;
    float4 xA, xB;
    {
        int ts = dir ? (T_ - 1) : 0;
        const float* xp = xrow + (size_t)ts * ID_;
        xA = *(const float4*)xp; xB = *(const float4*)(xp + 4);
    }

    const int hl = tid & 127, r0 = (tid >> 7) * 8;
    const int ghd = half * 128 + hl;
    float cst[8];
#pragma unroll
    for (int j = 0; j < 8; j++) cst[j] = 0.f;

    __syncthreads();
    CLUSTER_SYNC();

    for (int t = 0; t < T_; t++) {
        // stage x_t into [k][row] layout
#pragma unroll
        for (int j = 0; j < 4; j++) sm_x[(xc + j) * 16 + xr] = (&xA.x)[j];
#pragma unroll
        for (int j = 0; j < 4; j++) sm_x[(xc + 4 + j) * 16 + xr] = (&xB.x)[j];
        __syncthreads();

        // prefetch next x
        {
            int tn = (t + 1 < T_) ? t + 1 : t;
            int ts = dir ? (T_ - 1 - tn) : tn;
            const float* xp = xrow + (size_t)ts * ID_;
            xA = *(const float4*)xp; xB = *(const float4*)(xp + 4);
        }

        // gate GEMM: 16 rows x 2 cols per thread over k=384
        ull acc0[8], acc1[8];
#pragma unroll
        for (int j = 0; j < 8; j++) { acc0[j] = 0ull; acc1[j] = 0ull; }
        float2 wv[4][4];
        PREFW(0); PREFW(1); PREFW(2);
        const float* hb = sm_h + (t & 1) * 4096;
#pragma unroll 4
        for (int cx = 0; cx < 32; cx++) {
            PREFW(cx + 3);
            COMP4(cx, sm_x + cx * 64);
        }
#pragma unroll 4
        for (int ch = 0; ch < 64; ch++) {
            PREFW(35 + ch);
            COMP4(ch, hb + ch * 64);          // (32+ch)&3 == ch&3
        }

        // stage gates (+bias) to sm_g[row][col]
#pragma unroll
        for (int rp = 0; rp < 8; rp++) {
            float2 v0 = make_float2(lo32(acc0[rp]) + bs0, lo32(acc1[rp]) + bs1);
            float2 v1 = make_float2(hi32(acc0[rp]) + bs0, hi32(acc1[rp]) + bs1);
            *(float2*)&sm_g[(2 * rp) * 512 + 2 * tid] = v0;
            *(float2*)&sm_g[(2 * rp + 1) * 512 + 2 * tid] = v1;
        }
        __syncthreads();

        // cell update: thread owns hidden dim hl for 8 rows
        float hv[8];
#pragma unroll
        for (int j = 0; j < 8; j++) {
            const float* gr = sm_g + (r0 + j) * 512;
            float f = sigm(gr[hl]);
            float ii = sigm(gr[128 + hl]);
            float a = tanhp(gr[256 + hl]);
            float o = sigm(gr[384 + hl]);
            float cc = fmaf(f, cst[j], ii * a);
            cst[j] = cc;
            hv[j] = o * tanhp(cc);
        }

        // h -> own smem (next parity buffer)
        float* hw = sm_h + ((t + 1) & 1) * 4096 + ghd * 16 + r0;
        *(float4*)hw = make_float4(hv[0], hv[1], hv[2], hv[3]);
        *(float4*)(hw + 4) = make_float4(hv[4], hv[5], hv[6], hv[7]);
        // h -> peer smem via DSMEM
        unsigned la = (unsigned)__cvta_generic_to_shared(hw);
        unsigned pa;
        asm("mapa.shared::cluster.u32 %0, %1, %2;" : "=r"(pa) : "r"(la), "r"(rank ^ 1u));
        st_cluster64(pa,      pack2(hv[0], hv[1]));
        st_cluster64(pa + 8,  pack2(hv[2], hv[3]));
        st_cluster64(pa + 16, pack2(hv[4], hv[5]));
        st_cluster64(pa + 24, pack2(hv[6], hv[7]));
        // h -> global x1
        float* gx = g_x1 + ((size_t)(b0 + r0) * T_ + t) * (2 * HD_) + dir * HD_ + ghd;
#pragma unroll
        for (int j = 0; j < 8; j++) gx[(size_t)j * T_ * 2 * HD_] = hv[j];

        CLUSTER_SYNC();
    }
}

// ---------------- generic fp32x2 GEMM with bias + optional leaky-relu ----------------
template <int ACT>
__global__ __launch_bounds__(256) void gemm_kernel(const float* __restrict__ A,
                                                   const float* __restrict__ W,
                                                   const float* __restrict__ bias,
                                                   float* __restrict__ C,
                                                   int M, int N, int K) {
    __shared__ __align__(16) float smA[16][64];
    __shared__ __align__(16) float smW[16][128];

    const int tid = threadIdx.x;
    const int n0 = blockIdx.x * 128;
    const int m0 = blockIdx.y * 64;
    const int col = (tid & 31) * 4;
    const int rg = (tid >> 5) * 8;

    ull acc[4][4];
#pragma unroll
    for (int rp = 0; rp < 4; rp++)
#pragma unroll
        for (int c = 0; c < 4; c++) acc[rp][c] = 0ull;

    const int la_r = tid >> 2;
    const int la_k = (tid & 3) * 4;
    const int lw_n = (tid & 31) * 4;
    const int lw_k = tid >> 5;

    for (int k0 = 0; k0 < K; k0 += 16) {
        float4 av = *(const float4*)&A[(size_t)(m0 + la_r) * K + k0 + la_k];
        smA[la_k + 0][la_r] = av.x;
        smA[la_k + 1][la_r] = av.y;
        smA[la_k + 2][la_r] = av.z;
        smA[la_k + 3][la_r] = av.w;
        *(float4*)&smW[lw_k][lw_n]     = *(const float4*)&W[(size_t)(k0 + lw_k) * N + n0 + lw_n];
        *(float4*)&smW[lw_k + 8][lw_n] = *(const float4*)&W[(size_t)(k0 + lw_k + 8) * N + n0 + lw_n];
        __syncthreads();

#pragma unroll
        for (int kk = 0; kk < 16; kk++) {
            float4 wvv = *(const float4*)&smW[kk][col];
            ull wd0 = dupf(wvv.x), wd1 = dupf(wvv.y), wd2 = dupf(wvv.z), wd3 = dupf(wvv.w);
#pragma unroll
            for (int rp = 0; rp < 4; rp++) {
                ull hp = *(const ull*)&smA[kk][rg + 2 * rp];
                acc[rp][0] = fma2(hp, wd0, acc[rp][0]);
                acc[rp][1] = fma2(hp, wd1, acc[rp][1]);
                acc[rp][2] = fma2(hp, wd2, acc[rp][2]);
                acc[rp][3] = fma2(hp, wd3, acc[rp][3]);
            }
        }
        __syncthreads();
    }

    const float4 bv = *(const float4*)&bias[n0 + col];
#pragma unroll
    for (int rp = 0; rp < 4; rp++) {
        const int row0 = m0 + rg + 2 * rp;
        float4 v0, v1;
        v0.x = lo32(acc[rp][0]) + bv.x; v0.y = lo32(acc[rp][1]) + bv.y;
        v0.z = lo32(acc[rp][2]) + bv.z; v0.w = lo32(acc[rp][3]) + bv.w;
        v1.x = hi32(acc[rp][0]) + bv.x; v1.y = hi32(acc[rp][1]) + bv.y;
        v1.z = hi32(acc[rp][2]) + bv.z; v1.w = hi32(acc[rp][3]) + bv.w;
        if (ACT) {
            v0.x = fmaxf(v0.x, 0.1f * v0.x); v0.y = fmaxf(v0.y, 0.1f * v0.y);
            v0.z = fmaxf(v0.z, 0.1f * v0.z); v0.w = fmaxf(v0.w, 0.1f * v0.w);
            v1.x = fmaxf(v1.x, 0.1f * v1.x); v1.y = fmaxf(v1.y, 0.1f * v1.y);
            v1.z = fmaxf(v1.z, 0.1f * v1.z); v1.w = fmaxf(v1.w, 0.1f * v1.w);
        }
        *(float4*)&C[(size_t)row0 * N + n0 + col]       = v0;
        *(float4*)&C[(size_t)(row0 + 1) * N + n0 + col] = v1;
    }
}

// ---------------- head ----------------
__global__ __launch_bounds__(256) void head_kernel(float* __restrict__ out) {
    const int row = blockIdx.x * blockDim.x + threadIdx.x;
    if (row >= B_ * T_) return;
    const float* x = g_x4 + (size_t)row * OUTD_;
    float* o = out + (size_t)row * OUTD_;

#pragma unroll 4
    for (int j = 0; j < 64; j++) o[j] = sigm(x[j]);

    {
        float e[8]; float mx = -1e30f;
#pragma unroll
        for (int j = 0; j < 8; j++) { e[j] = x[64 + j]; mx = fmaxf(mx, e[j]); }
        float s = 0.f;
#pragma unroll
        for (int j = 0; j < 8; j++) { e[j] = __expf(e[j] - mx); s += e[j]; }
        float inv = 1.f / s;
#pragma unroll
        for (int j = 0; j < 8; j++) o[64 + j] = e[j] * inv;
    }
    {
        float e[16]; float mx = -1e30f;
#pragma unroll
        for (int j = 0; j < 16; j++) { e[j] = x[72 + j]; mx = fmaxf(mx, e[j]); }
        float s = 0.f;
#pragma unroll
        for (int j = 0; j < 16; j++) { e[j] = __expf(e[j] - mx); s += e[j]; }
        float inv = 1.f / s;
#pragma unroll
        for (int j = 0; j < 16; j++) o[72 + j] = e[j] * inv;
    }
    {
        float e[40]; float mx = -1e30f;
#pragma unroll
        for (int j = 0; j < 40; j++) { e[j] = x[88 + j]; mx = fmaxf(mx, e[j]); }
        float s = 0.f;
#pragma unroll
        for (int j = 0; j < 40; j++) { e[j] = __expf(e[j] - mx); s += e[j]; }
        float inv = 1.f / s;
#pragma unroll
        for (int j = 0; j < 40; j++) o[88 + j] = e[j] * inv;
    }
}

// ---------------- launch ----------------
extern "C" void kernel_launch(void* const* d_in, const int* in_sizes, int n_in,
                              void* d_out, int out_size) {
    (void)in_sizes; (void)n_in; (void)out_size;
    const float* x0   = (const float*)d_in[0];
    const float* Wi_f = (const float*)d_in[1];
    const float* bi_f = (const float*)d_in[2];
    const float* Wh_f = (const float*)d_in[3];
    const float* bh_f = (const float*)d_in[4];
    const float* Wi_r = (const float*)d_in[5];
    const float* bi_r = (const float*)d_in[6];
    const float* Wh_r = (const float*)d_in[7];
    const float* bh_r = (const float*)d_in[8];
    const float* W1   = (const float*)d_in[9];
    const float* b1   = (const float*)d_in[10];
    const float* W2   = (const float*)d_in[11];
    const float* b2   = (const float*)d_in[12];
    const float* W3   = (const float*)d_in[13];
    const float* b3   = (const float*)d_in[14];
    float* out = (float*)d_out;

    float *p_x1, *p_x2, *p_x3, *p_x4;
    cudaGetSymbolAddress((void**)&p_x1, g_x1);
    cudaGetSymbolAddress((void**)&p_x2, g_x2);
    cudaGetSymbolAddress((void**)&p_x3, g_x3);
    cudaGetSymbolAddress((void**)&p_x4, g_x4);

    static bool attr_set = false;
    if (!attr_set) {
        cudaFuncSetAttribute(lstm_kernel, cudaFuncAttributeMaxDynamicSharedMemorySize, 73728);
        attr_set = true;
    }

    prep_kernel<<<128, 256>>>(Wi_f, Wh_f, bi_f, bh_f, Wi_r, Wh_r, bi_r, bh_r);
    lstm_kernel<<<128, 256, 73728>>>(x0);

    const int M = B_ * T_;
    gemm_kernel<1><<<dim3(HD_ / 128, M / 64), 256>>>(p_x1, W1, b1, p_x2, M, HD_, 2 * HD_);
    gemm_kernel<1><<<dim3(HD_ / 128, M / 64), 256>>>(p_x2, W2, b2, p_x3, M, HD_, HD_);
    gemm_kernel<0><<<dim3(OUTD_ / 128, M / 64), 256>>>(p_x3, W3, b3, p_x4, M, OUTD_, HD_);
    head_kernel<<<(M + 255) / 256, 256>>>(out);
}